// round 8
// baseline (speedup 1.0000x reference)
#include <cuda_runtime.h>
#include <cstdint>

#define BB 64
#define PP 8732
#define OO 50
#define CC 81

// ---------------- scratch (device globals) ----------------
__device__ unsigned long long g_bestprior[BB * OO]; // packed (iou_bits<<32)|(~p)
__device__ int2   g_match[BB * PP];   // {iou_bits(float), best_truth_idx}
__device__ float  g_cerank[BB * PP];  // ce for negatives, 0 for positives
__device__ int    g_numpos[BB];
__device__ double g_lossl_b[BB];
__device__ double g_lossc_b[BB];
__device__ int    g_sync1;
__device__ int    g_sync5;

// ---------------- K0: zero ----------------
__global__ void k0_zero() {
    int i = blockIdx.x * blockDim.x + threadIdx.x;
    if (i < BB * OO) g_bestprior[i] = 0ull;
    if (i < BB) { g_numpos[i] = 0; g_lossl_b[i] = 0.0; g_lossc_b[i] = 0.0; }
    if (i == 0) { g_sync1 = 0; g_sync5 = 0; }
}

// ---------------- K1: matching + force-match override tail ----------------
#define TPB1 256
#define PPT 4
#define PPB (TPB1 * PPT)              // 1024
#define NBX ((PP + PPB - 1) / PPB)    // 9
#define NBLK1 (NBX * BB)              // 576

__global__ void k1_match(const float* __restrict__ targets,
                         const float* __restrict__ priors) {
    const int b = blockIdx.y;
    const int base = blockIdx.x * PPB;
    const int tid = threadIdx.x;

    __shared__ float s_t[OO][5]; // x1,y1,x2,y2,area

    for (int i = tid; i < OO; i += TPB1) {
        const float* t = targets + ((size_t)b * OO + i) * 5;
        float x1 = t[0], y1 = t[1], x2 = t[2], y2 = t[3];
        s_t[i][0] = x1; s_t[i][1] = y1; s_t[i][2] = x2; s_t[i][3] = y2;
        s_t[i][4] = (x2 - x1) * (y2 - y1);
    }
    __syncthreads();

    float px1[PPT], py1[PPT], px2[PPT], py2[PPT], pa[PPT];
    int   pp[PPT];
    float bi[PPT], bS[PPT]; int bo[PPT]; // per-prior best truth (inter, S=areaA+areaB)
#pragma unroll
    for (int j = 0; j < PPT; j++) {
        int p = base + tid + j * TPB1;
        pp[j] = p;
        if (p < PP) {
            float4 pr = *(const float4*)(priors + (size_t)p * 4);
            float x1 = pr.x - pr.z * 0.5f, y1 = pr.y - pr.w * 0.5f;
            float x2 = pr.x + pr.z * 0.5f, y2 = pr.y + pr.w * 0.5f;
            px1[j] = x1; py1[j] = y1; px2[j] = x2; py2[j] = y2;
            pa[j] = (x2 - x1) * (y2 - y1);
        } else {
            px1[j] = 4e9f; py1[j] = 4e9f; px2[j] = 4e9f; py2[j] = 4e9f;
            pa[j] = 0.f;
        }
        bi[j] = -1.f; bS[j] = 1.f; bo[j] = 0;
    }

    for (int o = 0; o < OO; o++) {
        const float tx1 = s_t[o][0], ty1 = s_t[o][1];
        const float tx2 = s_t[o][2], ty2 = s_t[o][3];
        const float ta  = s_t[o][4];

        // thread-local best prior for this truth: (ci, cS, cp)
        float ci = -1.f, cS = 1.f; int cp = 0x7FFFFFFF;
#pragma unroll
        for (int j = 0; j < PPT; j++) {
            float lx = fmaxf(tx1, px1[j]), ly = fmaxf(ty1, py1[j]);
            float rx = fminf(tx2, px2[j]), ry = fminf(ty2, py2[j]);
            float w = fmaxf(rx - lx, 0.f), h = fmaxf(ry - ly, 0.f);
            float inter = w * h;
            float S = ta + pa[j];
            // per-prior best-truth: iou compare == inter/S compare (monotone)
            if (inter * bS[j] > bi[j] * S) { bi[j] = inter; bS[j] = S; bo[j] = o; }
            // per-truth best-prior candidate
            float l = inter * cS, r = ci * S;
            if (l > r || (l == r && pp[j] < cp)) { ci = inter; cS = S; cp = pp[j]; }
        }
        // exact iou value (identical rounding to reference: inter/union)
        float q = __fdiv_rn(ci, cS - ci);
        unsigned long long key =
            ((unsigned long long)__float_as_uint(q) << 32) |
            (unsigned long long)(0xFFFFFFFFu - (unsigned)cp);
#pragma unroll
        for (int off = 16; off > 0; off >>= 1) {
            unsigned long long ok = __shfl_down_sync(0xFFFFFFFFu, key, off);
            if (ok > key) key = ok;
        }
        if ((tid & 31) == 0) atomicMax(&g_bestprior[b * OO + o], key);
    }

#pragma unroll
    for (int j = 0; j < PPT; j++) {
        if (pp[j] < PP) {
            float iou = __fdiv_rn(bi[j], bS[j] - bi[j]);
            g_match[(size_t)b * PP + pp[j]] = make_int2(__float_as_int(iou), bo[j]);
        }
    }

    // ---- tail: last block performs sequential last-wins override ----
    __threadfence();
    __shared__ int s_last;
    if (tid == 0) s_last = (atomicAdd(&g_sync1, 1) == NBLK1 - 1) ? 1 : 0;
    __syncthreads();
    if (s_last && tid < BB) {
        const int bb = tid;
        for (int o = 0; o < OO; o++) {
            unsigned long long key = __ldcg(&g_bestprior[bb * OO + o]);
            int p = (int)(0xFFFFFFFFu - (unsigned)(key & 0xFFFFFFFFull));
            g_match[(size_t)bb * PP + p] = make_int2(__float_as_int(2.0f), o);
        }
    }
}

// ---------------- KCE: CE + conf target + loc loss (fused) ----------------
__device__ __forceinline__ float sl1(float d) {
    float a = fabsf(d);
    return (a < 1.f) ? 0.5f * a * a : (a - 0.5f);
}

#define TPBC 512
#define WPB  (TPBC / 32)   // 16 warps per block
#define NBXC ((PP + WPB - 1) / WPB)  // 546

__global__ void kce(const float* __restrict__ conf,
                    const float* __restrict__ loc,
                    const float* __restrict__ targets,
                    const float* __restrict__ priors) {
    const int b = blockIdx.y;
    const int wid = threadIdx.x >> 5;
    const int lane = threadIdx.x & 31;
    const int p = blockIdx.x * WPB + wid;

    __shared__ double s_ll[WPB];
    __shared__ double s_ce[WPB];
    __shared__ int    s_np[WPB];

    double ll = 0.0, cev = 0.0;
    int np = 0;

    if (p < PP) {
        const size_t idx = (size_t)b * PP + p;
        const float* x = conf + idx * (size_t)CC;
        float x0 = x[lane];
        float x1 = x[lane + 32];
        float x2 = (lane < 17) ? x[lane + 64] : -3e38f;

        int t = 0;
        if (lane == 0) {
            int2 mm = g_match[idx];
            float ov = __int_as_float(mm.x);
            int o = mm.y;
            const float* tt = targets + ((size_t)b * OO + o) * 5;
            float m0 = tt[0], m1 = tt[1], m2 = tt[2], m3 = tt[3];
            t = (ov < 0.5f) ? 0 : ((int)tt[4] + 1);
            if (t > 0) {
                np = 1;
                float4 pr = *(const float4*)(priors + (size_t)p * 4);
                float gx = ((m0 + m2) * 0.5f - pr.x) / (0.1f * pr.z);
                float gy = ((m1 + m3) * 0.5f - pr.y) / (0.1f * pr.w);
                float gw = logf((m2 - m0) / pr.z) / 0.2f;
                float gh = logf((m3 - m1) / pr.w) / 0.2f;
                float4 L = *(const float4*)(loc + idx * 4);
                ll = (double)sl1(L.x - gx) + (double)sl1(L.y - gy)
                   + (double)sl1(L.z - gw) + (double)sl1(L.w - gh);
            }
        }
        t = __shfl_sync(0xFFFFFFFFu, t, 0);

        float m = fmaxf(fmaxf(x0, x1), x2);
#pragma unroll
        for (int off = 16; off > 0; off >>= 1)
            m = fmaxf(m, __shfl_xor_sync(0xFFFFFFFFu, m, off));
        float s = __expf(x0 - m) + __expf(x1 - m) + ((lane < 17) ? __expf(x2 - m) : 0.f);
#pragma unroll
        for (int off = 16; off > 0; off >>= 1)
            s += __shfl_xor_sync(0xFFFFFFFFu, s, off);
        float xt = (lane == t) ? x0 : ((lane + 32 == t) ? x1 : ((lane + 64 == t) ? x2 : 0.f));
#pragma unroll
        for (int off = 16; off > 0; off >>= 1)
            xt += __shfl_xor_sync(0xFFFFFFFFu, xt, off);

        if (lane == 0) {
            float ce = __logf(s) + m - xt;
            if (t > 0) { cev = (double)ce; g_cerank[idx] = 0.f; }
            else       { g_cerank[idx] = ce; }
        }
    }

    if (lane == 0) { s_ll[wid] = ll; s_ce[wid] = cev; s_np[wid] = np; }
    __syncthreads();
    if (threadIdx.x == 0) {
        double a = 0.0, c = 0.0; int n = 0;
#pragma unroll
        for (int w = 0; w < WPB; w++) { a += s_ll[w]; c += s_ce[w]; n += s_np[w]; }
        if (n) atomicAdd(&g_numpos[b], n);
        if (a != 0.0) atomicAdd(&g_lossl_b[b], a);
        if (c != 0.0) atomicAdd(&g_lossc_b[b], c);
    }
}

// ---------------- K5: hard-negative mining + finalize tail ----------------
__global__ void k5_mine(float* __restrict__ out) {
    __shared__ unsigned sk[PP];
    __shared__ int s_part[32];
    __shared__ unsigned s_state[2]; // prefix, kk
    __shared__ double s_sumd[32];
    __shared__ int s_cg[32];

    const int b = blockIdx.x;
    const int tid = threadIdx.x;
    const int T = 1024;
    const int wid = tid >> 5, lane = tid & 31;

    for (int i = tid; i < PP; i += T)
        sk[i] = __float_as_uint(g_cerank[(size_t)b * PP + i]);
    int np = g_numpos[b];
    int k = min(3 * np, PP - 1);
    if (tid == 0) { s_state[0] = 0u; s_state[1] = (unsigned)k; }
    __syncthreads();

    if (k > 0) {
        // exact radix-select of k-th largest key (bit31 always 0: ce >= 0)
        for (int bit = 30; bit >= 0; bit--) {
            unsigned prefix = s_state[0];
            unsigned kk = s_state[1];
            unsigned candhi = (prefix | (1u << bit)) >> bit;
            int c = 0;
            for (int i = tid; i < PP; i += T) c += ((sk[i] >> bit) == candhi);
#pragma unroll
            for (int off = 16; off > 0; off >>= 1)
                c += __shfl_down_sync(0xFFFFFFFFu, c, off);
            if (lane == 0) s_part[wid] = c;
            __syncthreads();
            if (wid == 0) {
                int v = s_part[lane];
#pragma unroll
                for (int off = 16; off > 0; off >>= 1)
                    v += __shfl_down_sync(0xFFFFFFFFu, v, off);
                if (lane == 0) {
                    if ((unsigned)v >= kk) s_state[0] = prefix | (1u << bit);
                    else                   s_state[1] = kk - (unsigned)v;
                }
            }
            __syncthreads();
        }

        const unsigned T0 = s_state[0];
        double s = 0.0; int cg = 0;
        for (int i = tid; i < PP; i += T) {
            unsigned key = sk[i];
            if (key > T0) { s += (double)__uint_as_float(key); cg++; }
        }
#pragma unroll
        for (int off = 16; off > 0; off >>= 1) {
            s += __shfl_down_sync(0xFFFFFFFFu, s, off);
            cg += __shfl_down_sync(0xFFFFFFFFu, cg, off);
        }
        if (lane == 0) { s_sumd[wid] = s; s_cg[wid] = cg; }
        __syncthreads();
        if (tid == 0) {
            double tot = 0.0; int c = 0;
#pragma unroll
            for (int w = 0; w < 32; w++) { tot += s_sumd[w]; c += s_cg[w]; }
            tot += (double)(k - c) * (double)__uint_as_float(T0);
            atomicAdd(&g_lossc_b[b], tot);
        }
    }

    // ---- tail: last block finalizes output ----
    __threadfence();
    if (tid == 0) {
        if (atomicAdd(&g_sync5, 1) == BB - 1) {
            double ll = 0.0, lc = 0.0; int N = 0;
            for (int i = 0; i < BB; i++) {
                N  += __ldcg(&g_numpos[i]);
                ll += __ldcg(&g_lossl_b[i]);
                lc += __ldcg(&g_lossc_b[i]);
            }
            double Nd = (double)N;
            out[0] = (float)(ll / Nd);
            out[1] = (float)(lc / Nd);
        }
    }
}

// ---------------- launch ----------------
extern "C" void kernel_launch(void* const* d_in, const int* in_sizes, int n_in,
                              void* d_out, int out_size) {
    const float* loc     = (const float*)d_in[0];
    const float* conf    = (const float*)d_in[1];
    const float* targets = (const float*)d_in[2];
    const float* priors  = (const float*)d_in[3];
    float* out = (float*)d_out;

    k0_zero<<<(BB * OO + 255) / 256, 256>>>();
    k1_match<<<dim3(NBX, BB), TPB1>>>(targets, priors);
    kce<<<dim3(NBXC, BB), TPBC>>>(conf, loc, targets, priors);
    k5_mine<<<BB, 1024>>>(out);
}